// round 14
// baseline (speedup 1.0000x reference)
#include <cuda_runtime.h>
#include <cuda_bf16.h>
#include <cstdint>

#define NN 100000
#define NE 600000
#define NV 50000
#define DIM 128
#define NNZ (NE + NN)
#define CHUNK ((NN + 1023) / 1024)   // 98

#define TILES1 ((NV + 63) / 64)     // 782
#define TILES2 ((NN + 63) / 64)     // 1563

// ---------------- scratch (static device globals; no allocation) ----------
__device__ int   g_deg[NN];                  // EDGE degree only (self-loop folded)
__device__ int   g_rowptr[NN + 1];
__device__ int   g_cursor[NN];
__device__ int   g_col[NNZ];
__device__ float g_dinv[NN];
__device__ uint4 g_Wf[2 * 16 * 8 * 32];      // W frags hi/lo packed
__device__ float g_embW[(size_t)NV * DIM];   // emb @ W1
__device__ float g_agg [(size_t)NN * DIM];   // layer-1 output h1
__device__ float g_hw  [(size_t)NN * DIM];   // layer-2 pre-agg

// ---------------- degree / CSR build ---------------------------------------
__global__ void k_count_deg(const int* __restrict__ dst) {
    int e = blockIdx.x * blockDim.x + threadIdx.x;
    if (e < NE) atomicAdd(&g_deg[dst[e]], 1);
}
__global__ __launch_bounds__(1024) void k_scan_fused() {
    __shared__ int s[1024];
    int tid = threadIdx.x;
    int lo = tid * CHUNK;
    int hi = lo + CHUNK; if (hi > NN) hi = NN;
    int sum = 0;
    #pragma unroll 4
    for (int i = lo; i < hi; i++) sum += g_deg[i] + 1;
    s[tid] = sum;
    __syncthreads();
    #pragma unroll
    for (int off = 1; off < 1024; off <<= 1) {
        int t = (tid >= off) ? s[tid - off] : 0;
        __syncthreads();
        s[tid] += t;
        __syncthreads();
    }
    int run = (tid == 0) ? 0 : s[tid - 1];
    #pragma unroll 4
    for (int i = lo; i < hi; i++) { g_rowptr[i] = run; run += g_deg[i] + 1; }
    if (tid == 1023) g_rowptr[NN] = run;
}
__global__ void k_fill_init() {
    int i = blockIdx.x * blockDim.x + threadIdx.x;
    if (i < NN) {
        int base = g_rowptr[i];
        g_col[base] = i;
        g_cursor[i] = base + 1;
        g_dinv[i] = rsqrtf((float)(g_deg[i] + 1));
    }
}
__global__ void k_fill_edges(const int* __restrict__ src, const int* __restrict__ dst) {
    int e = blockIdx.x * blockDim.x + threadIdx.x;
    if (e < NE) {
        int pos = atomicAdd(&g_cursor[dst[e]], 1);
        g_col[pos] = src[e];
    }
}

// ---------------- helpers ---------------------------------------------------
__device__ __forceinline__ uint32_t pack_bf16(float lo_val, float hi_val) {
    uint32_t d;
    asm("cvt.rn.bf16x2.f32 %0, %1, %2;" : "=r"(d) : "f"(hi_val), "f"(lo_val));
    return d;
}
__device__ __forceinline__ float bf16lo_to_f32(uint32_t p) { return __uint_as_float(p << 16); }
__device__ __forceinline__ float bf16hi_to_f32(uint32_t p) { return __uint_as_float(p & 0xFFFF0000u); }

__device__ __forceinline__ void mma_bf16(float* c, const uint32_t* a, uint32_t b0, uint32_t b1) {
    asm volatile(
        "mma.sync.aligned.m16n8k16.row.col.f32.bf16.bf16.f32 "
        "{%0,%1,%2,%3}, {%4,%5,%6,%7}, {%8,%9}, {%0,%1,%2,%3};"
        : "+f"(c[0]), "+f"(c[1]), "+f"(c[2]), "+f"(c[3])
        : "r"(a[0]), "r"(a[1]), "r"(a[2]), "r"(a[3]), "r"(b0), "r"(b1));
}

__global__ void k_prep_wf(const float* __restrict__ W1, const float* __restrict__ W2) {
    int gid = blockIdx.x * blockDim.x + threadIdx.x;   // 8192 total
    if (gid >= 2 * 16 * 8 * 32) return;
    int lane  = gid & 31;
    int kt    = (gid >> 5) & 7;
    int nt    = (gid >> 8) & 15;
    int layer = gid >> 12;
    const float* W = layer ? W2 : W1;
    int n  = nt * 8 + (lane >> 2);
    int k0 = kt * 16 + (lane & 3) * 2;

    float v[4];
    v[0] = W[(k0    ) * DIM + n];
    v[1] = W[(k0 + 1) * DIM + n];
    v[2] = W[(k0 + 8) * DIM + n];
    v[3] = W[(k0 + 9) * DIM + n];
    float h[4], l[4];
    #pragma unroll
    for (int j = 0; j < 4; j++) {
        __nv_bfloat16 hb = __float2bfloat16_rn(v[j]);
        h[j] = __bfloat162float(hb);
        l[j] = v[j] - h[j];
    }
    g_Wf[gid] = make_uint4(pack_bf16(h[0], h[1]), pack_bf16(h[2], h[3]),
                           pack_bf16(l[0], l[1]), pack_bf16(l[2], l[3]));
}

// ---------------- GEMM via mma.sync bf16 split (3-pass), tile-offset --------
#define SA_STRIDE 68
#define SMEM_GEMM (2 * 64 * SA_STRIDE * 4)    // 34816 B

__global__ __launch_bounds__(256, 3) void k_gemm_mma(
    const float* __restrict__ A, const uint4* __restrict__ Wf,
    float* __restrict__ C, int M, int tile_base)
{
    extern __shared__ uint32_t sAu[];
    uint32_t* sAh = sAu;
    uint32_t* sAl = sAu + 64 * SA_STRIDE;
    int tid = threadIdx.x;
    int wid = tid >> 5;
    int lane = tid & 31;
    int row0 = (tile_base + blockIdx.x) * 64;
    int rows_left = M - row0;

    {
        const float4* Av = (const float4*)(A + (size_t)row0 * DIM);
        #pragma unroll
        for (int i = 0; i < 8; i++) {
            int idx = tid + i * 256;
            int r = idx >> 5, c4 = idx & 31;
            float4 v = make_float4(0.f, 0.f, 0.f, 0.f);
            if (r < rows_left) v = __ldcs(Av + idx);
            uint32_t h0 = pack_bf16(v.x, v.y);
            uint32_t h1 = pack_bf16(v.z, v.w);
            uint32_t l0 = pack_bf16(v.x - bf16lo_to_f32(h0), v.y - bf16hi_to_f32(h0));
            uint32_t l1 = pack_bf16(v.z - bf16lo_to_f32(h1), v.w - bf16hi_to_f32(h1));
            *(uint2*)&sAh[r * SA_STRIDE + c4 * 2] = make_uint2(h0, h1);
            *(uint2*)&sAl[r * SA_STRIDE + c4 * 2] = make_uint2(l0, l1);
        }
    }
    __syncthreads();

    int wr = wid >> 2;
    int wc = wid & 3;
    int q  = lane >> 2;
    int w  = lane & 3;

    float acc[2][4][4];
    #pragma unroll
    for (int m = 0; m < 2; m++)
        #pragma unroll
        for (int j = 0; j < 4; j++)
            acc[m][j][0] = acc[m][j][1] = acc[m][j][2] = acc[m][j][3] = 0.f;

    int rA = (wr * 32 + q) * SA_STRIDE;
    const uint4* pb0 = Wf + wc * 1024 + lane;

    #pragma unroll
    for (int kt = 0; kt < 8; kt++) {
        int kp = kt * 8 + w;
        uint32_t ah0[4], al0[4], ah1[4], al1[4];
        ah0[0] = sAh[rA + kp];                    ah0[1] = sAh[rA + 8  * SA_STRIDE + kp];
        ah0[2] = sAh[rA + kp + 4];                ah0[3] = sAh[rA + 8  * SA_STRIDE + kp + 4];
        ah1[0] = sAh[rA + 16 * SA_STRIDE + kp];   ah1[1] = sAh[rA + 24 * SA_STRIDE + kp];
        ah1[2] = sAh[rA + 16 * SA_STRIDE + kp+4]; ah1[3] = sAh[rA + 24 * SA_STRIDE + kp + 4];
        al0[0] = sAl[rA + kp];                    al0[1] = sAl[rA + 8  * SA_STRIDE + kp];
        al0[2] = sAl[rA + kp + 4];                al0[3] = sAl[rA + 8  * SA_STRIDE + kp + 4];
        al1[0] = sAl[rA + 16 * SA_STRIDE + kp];   al1[1] = sAl[rA + 24 * SA_STRIDE + kp];
        al1[2] = sAl[rA + 16 * SA_STRIDE + kp+4]; al1[3] = sAl[rA + 24 * SA_STRIDE + kp + 4];

        const uint4* pb = pb0 + kt * 32;
        uint4 b[4];
        #pragma unroll
        for (int j = 0; j < 4; j++)
            b[j] = __ldg(pb + j * 256);

        #pragma unroll
        for (int j = 0; j < 4; j++) {
            mma_bf16(acc[0][j], ah0, b[j].x, b[j].y);
            mma_bf16(acc[1][j], ah1, b[j].x, b[j].y);
        }
        #pragma unroll
        for (int j = 0; j < 4; j++) {
            mma_bf16(acc[0][j], al0, b[j].x, b[j].y);
            mma_bf16(acc[1][j], al1, b[j].x, b[j].y);
        }
        #pragma unroll
        for (int j = 0; j < 4; j++) {
            mma_bf16(acc[0][j], ah0, b[j].z, b[j].w);
            mma_bf16(acc[1][j], ah1, b[j].z, b[j].w);
        }
    }

    #pragma unroll
    for (int m = 0; m < 2; m++) {
        int rr0 = row0 + wr * 32 + m * 16 + q;
        int rr1 = rr0 + 8;
        #pragma unroll
        for (int j = 0; j < 4; j++) {
            int col = (wc * 4 + j) * 8 + w * 2;
            if (rr0 < M)
                *(float2*)&C[(size_t)rr0 * DIM + col] = make_float2(acc[m][j][0], acc[m][j][1]);
            if (rr1 < M)
                *(float2*)&C[(size_t)rr1 * DIM + col] = make_float2(acc[m][j][2], acc[m][j][3]);
        }
    }
}

// ---------------- SpMM gather (R11/R13 structure), node-range ---------------
template<bool LAYER1>
__global__ __launch_bounds__(256) void k_spmm(
    const float* __restrict__ feat, const int* __restrict__ x,
    const float* __restrict__ bias, float* __restrict__ out,
    int node_base, int node_count)
{
    int local = (int)((blockIdx.x * blockDim.x + threadIdx.x) >> 5);
    if (local >= node_count) return;
    int node = node_base + local;
    int lane = threadIdx.x & 31;

    int start = g_rowptr[node];
    int end   = g_rowptr[node + 1];
    const float4* f4 = (const float4*)feat;

    float ax = 0.f, ay = 0.f, az = 0.f, aw = 0.f;
    int k = start;
    for (; k + 3 < end; k += 4) {
        int c0 = g_col[k],     c1 = g_col[k + 1];
        int c2 = g_col[k + 2], c3 = g_col[k + 3];
        float w0 = g_dinv[c0], w1 = g_dinv[c1];
        float w2 = g_dinv[c2], w3 = g_dinv[c3];
        int r0 = LAYER1 ? x[c0] : c0;
        int r1 = LAYER1 ? x[c1] : c1;
        int r2 = LAYER1 ? x[c2] : c2;
        int r3 = LAYER1 ? x[c3] : c3;
        float4 v0 = f4[(size_t)r0 * 32 + lane];
        float4 v1 = f4[(size_t)r1 * 32 + lane];
        float4 v2 = f4[(size_t)r2 * 32 + lane];
        float4 v3 = f4[(size_t)r3 * 32 + lane];
        ax = fmaf(w0, v0.x, ax); ay = fmaf(w0, v0.y, ay);
        az = fmaf(w0, v0.z, az); aw = fmaf(w0, v0.w, aw);
        ax = fmaf(w1, v1.x, ax); ay = fmaf(w1, v1.y, ay);
        az = fmaf(w1, v1.z, az); aw = fmaf(w1, v1.w, aw);
        ax = fmaf(w2, v2.x, ax); ay = fmaf(w2, v2.y, ay);
        az = fmaf(w2, v2.z, az); aw = fmaf(w2, v2.w, aw);
        ax = fmaf(w3, v3.x, ax); ay = fmaf(w3, v3.y, ay);
        az = fmaf(w3, v3.z, az); aw = fmaf(w3, v3.w, aw);
    }
    for (; k < end; k++) {
        int c = g_col[k];
        float w = g_dinv[c];
        int r = LAYER1 ? x[c] : c;
        float4 v = f4[(size_t)r * 32 + lane];
        ax = fmaf(w, v.x, ax); ay = fmaf(w, v.y, ay);
        az = fmaf(w, v.z, az); aw = fmaf(w, v.w, aw);
    }

    float di = g_dinv[node];
    float4 b = __ldg((const float4*)bias + lane);
    float4 o;
    o.x = fmaxf(fmaf(di, ax, b.x), 0.f);
    o.y = fmaxf(fmaf(di, ay, b.y), 0.f);
    o.z = fmaxf(fmaf(di, az, b.z), 0.f);
    o.w = fmaxf(fmaf(di, aw, b.w), 0.f);
    __stcs((float4*)out + (size_t)node * 32 + lane, o);
}

// ---------------- launch ----------------------------------------------------
// Two overlaps: (1) CSR build || prep_wf+gemm1 (R13); (2) spmm1 and gemm2
// chunk-pipelined: gemm2 tile-chunk i depends only on spmm1 node-chunk i
// (gemm2 is row-local). spmm2 gathers neighbor rows -> waits for all gemm2.
extern "C" void kernel_launch(void* const* d_in, const int* in_sizes, int n_in,
                              void* d_out, int out_size) {
    const int*   x   = (const int*)d_in[0];
    const int*   src = (const int*)d_in[1];
    const int*   dst = src + NE;
    const float* emb = (const float*)d_in[2];
    const float* W1  = (const float*)d_in[3];
    const float* b1  = (const float*)d_in[4];
    const float* W2  = (const float*)d_in[5];
    const float* b2  = (const float*)d_in[6];
    float*       out = (float*)d_out;

    float *p_embW, *p_agg, *p_hw;
    uint4 *p_Wf;
    int   *p_deg;
    cudaGetSymbolAddress((void**)&p_embW, g_embW);
    cudaGetSymbolAddress((void**)&p_agg,  g_agg);
    cudaGetSymbolAddress((void**)&p_hw,   g_hw);
    cudaGetSymbolAddress((void**)&p_Wf,   g_Wf);
    cudaGetSymbolAddress((void**)&p_deg,  g_deg);

    cudaFuncSetAttribute(k_gemm_mma, cudaFuncAttributeMaxDynamicSharedMemorySize, SMEM_GEMM);

    cudaStream_t s2;
    cudaEvent_t ev_fork, ev_join, ev_s1[4], ev_g2;
    cudaStreamCreateWithFlags(&s2, cudaStreamNonBlocking);
    cudaEventCreateWithFlags(&ev_fork, cudaEventDisableTiming);
    cudaEventCreateWithFlags(&ev_join, cudaEventDisableTiming);
    for (int i = 0; i < 4; i++) cudaEventCreateWithFlags(&ev_s1[i], cudaEventDisableTiming);
    cudaEventCreateWithFlags(&ev_g2, cudaEventDisableTiming);

    // fork
    cudaEventRecord(ev_fork, 0);
    cudaStreamWaitEvent(s2, ev_fork, 0);

    // Phase 1: CSR (s2)  ||  prep_wf + gemm1 (main)
    cudaMemsetAsync(p_deg, 0, NN * sizeof(int), s2);
    k_count_deg <<<(NE + 255) / 256, 256, 0, s2>>>(dst);                  // #1
    k_prep_wf   <<<(2 * 16 * 8 * 32 + 255) / 256, 256>>>(W1, W2);         // #2
    k_scan_fused<<<1, 1024, 0, s2>>>();                                   // #3
    k_gemm_mma  <<<TILES1, 256, SMEM_GEMM>>>(emb, p_Wf, p_embW, NV, 0);   // #4 <- profiled
    k_fill_init <<<(NN + 255) / 256, 256, 0, s2>>>();                     // #5
    k_fill_edges<<<(NE + 255) / 256, 256, 0, s2>>>(src, dst);             // #6

    // join: spmm1 needs CSR + gemm1
    cudaEventRecord(ev_join, s2);
    cudaStreamWaitEvent(0, ev_join, 0);

    // Phase 2: spmm1 chunks (main) pipelined with gemm2 chunks (s2)
    const int tile_chunk[4] = {391, 391, 391, 390};
    int tbase = 0;
    for (int i = 0; i < 4; i++) {
        int nbase = tbase * 64;
        int ncnt  = tile_chunk[i] * 64;
        if (nbase + ncnt > NN) ncnt = NN - nbase;
        int nblocks = (ncnt + 7) / 8;
        k_spmm<true><<<nblocks, 256>>>(p_embW, x, b1, p_agg, nbase, ncnt);
        cudaEventRecord(ev_s1[i], 0);
        cudaStreamWaitEvent(s2, ev_s1[i], 0);
        k_gemm_mma<<<tile_chunk[i], 256, SMEM_GEMM, s2>>>(p_agg, p_Wf + 16 * 8 * 32,
                                                          p_hw, NN, tbase);
        tbase += tile_chunk[i];
    }

    // join: spmm2 needs all of hw
    cudaEventRecord(ev_g2, s2);
    cudaStreamWaitEvent(0, ev_g2, 0);

    k_spmm<false><<<(NN + 7) / 8, 256>>>(p_hw, x, b2, out, 0, NN);
}

// round 15
// speedup vs baseline: 1.1376x; 1.1376x over previous
#include <cuda_runtime.h>
#include <cuda_bf16.h>
#include <cstdint>

#define NN 100000
#define NE 600000
#define NV 50000
#define DIM 128
#define NNZP (NE + 4 * NN)           // padded CSR capacity (pad <= +3/node + self)
#define CHUNK ((NN + 1023) / 1024)   // 98

#define TILES1 ((NV + 63) / 64)     // 782
#define TILES2 ((NN + 63) / 64)     // 1563

// ---------------- scratch (static device globals; no allocation) ----------
__device__ int   g_deg[NN];                  // EDGE degree only
__device__ int   g_rowptr[NN + 1];           // padded to multiples of 4
__device__ int   g_cursor[NN];
__device__ float g_dinv[NN];
__device__ int   g_r1[NNZP];                 // layer-1 gather row = x[src]
__device__ int   g_r2[NNZP];                 // layer-2 gather row = src
__device__ float g_w [NNZP];                 // edge weight = dinv[src] (0 for pad)
__device__ uint4 g_Wf[2 * 16 * 8 * 32];      // W frags hi/lo packed
__device__ float g_embW[(size_t)NV * DIM];   // emb @ W1
__device__ float g_agg [(size_t)NN * DIM];   // layer-1 output h1
__device__ float g_hw  [(size_t)NN * DIM];   // layer-2 pre-agg

// ---------------- degree / CSR build ---------------------------------------
__global__ void k_count_deg(const int* __restrict__ dst) {
    int e = blockIdx.x * blockDim.x + threadIdx.x;
    if (e < NE) atomicAdd(&g_deg[dst[e]], 1);
}
// Single-block exclusive scan of pad4(deg+1) -> g_rowptr.
__global__ __launch_bounds__(1024) void k_scan_fused() {
    __shared__ int s[1024];
    int tid = threadIdx.x;
    int lo = tid * CHUNK;
    int hi = lo + CHUNK; if (hi > NN) hi = NN;
    int sum = 0;
    #pragma unroll 4
    for (int i = lo; i < hi; i++) sum += (g_deg[i] + 4) & ~3;
    s[tid] = sum;
    __syncthreads();
    #pragma unroll
    for (int off = 1; off < 1024; off <<= 1) {
        int t = (tid >= off) ? s[tid - off] : 0;
        __syncthreads();
        s[tid] += t;
        __syncthreads();
    }
    int run = (tid == 0) ? 0 : s[tid - 1];
    #pragma unroll 4
    for (int i = lo; i < hi; i++) { g_rowptr[i] = run; run += (g_deg[i] + 4) & ~3; }
    if (tid == 1023) g_rowptr[NN] = run;
}
__global__ void k_fill_init(const int* __restrict__ x) {
    int i = blockIdx.x * blockDim.x + threadIdx.x;
    if (i < NN) {
        int base = g_rowptr[i];
        int d    = g_deg[i];
        float di = rsqrtf((float)(d + 1));
        g_dinv[i] = di;
        // self-loop entry first
        g_r1[base] = x[i];
        g_r2[base] = i;
        g_w [base] = di;
        g_cursor[i] = base + 1;
        // zero-weight padding (row 0 is a safe dummy)
        int end_real = base + 1 + d;
        int end_pad  = g_rowptr[i + 1];
        for (int k = end_real; k < end_pad; k++) {
            g_r1[k] = 0; g_r2[k] = 0; g_w[k] = 0.f;
        }
    }
}
__global__ void k_fill_edges(const int* __restrict__ src, const int* __restrict__ dst,
                             const int* __restrict__ x) {
    int e = blockIdx.x * blockDim.x + threadIdx.x;
    if (e < NE) {
        int s = src[e];
        int pos = atomicAdd(&g_cursor[dst[e]], 1);
        g_r2[pos] = s;
        g_r1[pos] = x[s];
        g_w [pos] = g_dinv[s];
    }
}

// ---------------- helpers ---------------------------------------------------
__device__ __forceinline__ uint32_t pack_bf16(float lo_val, float hi_val) {
    uint32_t d;
    asm("cvt.rn.bf16x2.f32 %0, %1, %2;" : "=r"(d) : "f"(hi_val), "f"(lo_val));
    return d;
}
__device__ __forceinline__ float bf16lo_to_f32(uint32_t p) { return __uint_as_float(p << 16); }
__device__ __forceinline__ float bf16hi_to_f32(uint32_t p) { return __uint_as_float(p & 0xFFFF0000u); }

__device__ __forceinline__ void mma_bf16(float* c, const uint32_t* a, uint32_t b0, uint32_t b1) {
    asm volatile(
        "mma.sync.aligned.m16n8k16.row.col.f32.bf16.bf16.f32 "
        "{%0,%1,%2,%3}, {%4,%5,%6,%7}, {%8,%9}, {%0,%1,%2,%3};"
        : "+f"(c[0]), "+f"(c[1]), "+f"(c[2]), "+f"(c[3])
        : "r"(a[0]), "r"(a[1]), "r"(a[2]), "r"(a[3]), "r"(b0), "r"(b1));
}

__global__ void k_prep_wf(const float* __restrict__ W1, const float* __restrict__ W2) {
    int gid = blockIdx.x * blockDim.x + threadIdx.x;   // 8192 total
    if (gid >= 2 * 16 * 8 * 32) return;
    int lane  = gid & 31;
    int kt    = (gid >> 5) & 7;
    int nt    = (gid >> 8) & 15;
    int layer = gid >> 12;
    const float* W = layer ? W2 : W1;
    int n  = nt * 8 + (lane >> 2);
    int k0 = kt * 16 + (lane & 3) * 2;

    float v[4];
    v[0] = W[(k0    ) * DIM + n];
    v[1] = W[(k0 + 1) * DIM + n];
    v[2] = W[(k0 + 8) * DIM + n];
    v[3] = W[(k0 + 9) * DIM + n];
    float h[4], l[4];
    #pragma unroll
    for (int j = 0; j < 4; j++) {
        __nv_bfloat16 hb = __float2bfloat16_rn(v[j]);
        h[j] = __bfloat162float(hb);
        l[j] = v[j] - h[j];
    }
    g_Wf[gid] = make_uint4(pack_bf16(h[0], h[1]), pack_bf16(h[2], h[3]),
                           pack_bf16(l[0], l[1]), pack_bf16(l[2], l[3]));
}

// ---------------- GEMM via mma.sync bf16 split (3-pass) --------------------
#define SA_STRIDE 68
#define SMEM_GEMM (2 * 64 * SA_STRIDE * 4)    // 34816 B

__global__ __launch_bounds__(256, 3) void k_gemm_mma(
    const float* __restrict__ A, const uint4* __restrict__ Wf,
    float* __restrict__ C, int M)
{
    extern __shared__ uint32_t sAu[];
    uint32_t* sAh = sAu;
    uint32_t* sAl = sAu + 64 * SA_STRIDE;
    int tid = threadIdx.x;
    int wid = tid >> 5;
    int lane = tid & 31;
    int row0 = blockIdx.x * 64;
    int rows_left = M - row0;

    {
        const float4* Av = (const float4*)(A + (size_t)row0 * DIM);
        #pragma unroll
        for (int i = 0; i < 8; i++) {
            int idx = tid + i * 256;
            int r = idx >> 5, c4 = idx & 31;
            float4 v = make_float4(0.f, 0.f, 0.f, 0.f);
            if (r < rows_left) v = __ldcs(Av + idx);
            uint32_t h0 = pack_bf16(v.x, v.y);
            uint32_t h1 = pack_bf16(v.z, v.w);
            uint32_t l0 = pack_bf16(v.x - bf16lo_to_f32(h0), v.y - bf16hi_to_f32(h0));
            uint32_t l1 = pack_bf16(v.z - bf16lo_to_f32(h1), v.w - bf16hi_to_f32(h1));
            *(uint2*)&sAh[r * SA_STRIDE + c4 * 2] = make_uint2(h0, h1);
            *(uint2*)&sAl[r * SA_STRIDE + c4 * 2] = make_uint2(l0, l1);
        }
    }
    __syncthreads();

    int wr = wid >> 2;
    int wc = wid & 3;
    int q  = lane >> 2;
    int w  = lane & 3;

    float acc[2][4][4];
    #pragma unroll
    for (int m = 0; m < 2; m++)
        #pragma unroll
        for (int j = 0; j < 4; j++)
            acc[m][j][0] = acc[m][j][1] = acc[m][j][2] = acc[m][j][3] = 0.f;

    int rA = (wr * 32 + q) * SA_STRIDE;
    const uint4* pb0 = Wf + wc * 1024 + lane;

    #pragma unroll
    for (int kt = 0; kt < 8; kt++) {
        int kp = kt * 8 + w;
        uint32_t ah0[4], al0[4], ah1[4], al1[4];
        ah0[0] = sAh[rA + kp];                    ah0[1] = sAh[rA + 8  * SA_STRIDE + kp];
        ah0[2] = sAh[rA + kp + 4];                ah0[3] = sAh[rA + 8  * SA_STRIDE + kp + 4];
        ah1[0] = sAh[rA + 16 * SA_STRIDE + kp];   ah1[1] = sAh[rA + 24 * SA_STRIDE + kp];
        ah1[2] = sAh[rA + 16 * SA_STRIDE + kp+4]; ah1[3] = sAh[rA + 24 * SA_STRIDE + kp + 4];
        al0[0] = sAl[rA + kp];                    al0[1] = sAl[rA + 8  * SA_STRIDE + kp];
        al0[2] = sAl[rA + kp + 4];                al0[3] = sAl[rA + 8  * SA_STRIDE + kp + 4];
        al1[0] = sAl[rA + 16 * SA_STRIDE + kp];   al1[1] = sAl[rA + 24 * SA_STRIDE + kp];
        al1[2] = sAl[rA + 16 * SA_STRIDE + kp+4]; al1[3] = sAl[rA + 24 * SA_STRIDE + kp + 4];

        const uint4* pb = pb0 + kt * 32;
        uint4 b[4];
        #pragma unroll
        for (int j = 0; j < 4; j++)
            b[j] = __ldg(pb + j * 256);

        #pragma unroll
        for (int j = 0; j < 4; j++) {
            mma_bf16(acc[0][j], ah0, b[j].x, b[j].y);
            mma_bf16(acc[1][j], ah1, b[j].x, b[j].y);
        }
        #pragma unroll
        for (int j = 0; j < 4; j++) {
            mma_bf16(acc[0][j], al0, b[j].x, b[j].y);
            mma_bf16(acc[1][j], al1, b[j].x, b[j].y);
        }
        #pragma unroll
        for (int j = 0; j < 4; j++) {
            mma_bf16(acc[0][j], ah0, b[j].z, b[j].w);
            mma_bf16(acc[1][j], ah1, b[j].z, b[j].w);
        }
    }

    #pragma unroll
    for (int m = 0; m < 2; m++) {
        int rr0 = row0 + wr * 32 + m * 16 + q;
        int rr1 = rr0 + 8;
        #pragma unroll
        for (int j = 0; j < 4; j++) {
            int col = (wc * 4 + j) * 8 + w * 2;
            if (rr0 < M)
                *(float2*)&C[(size_t)rr0 * DIM + col] = make_float2(acc[m][j][0], acc[m][j][1]);
            if (rr1 < M)
                *(float2*)&C[(size_t)rr1 * DIM + col] = make_float2(acc[m][j][2], acc[m][j][3]);
        }
    }
}

// ---------------- SpMM gather: padded rows, vectorized edge meta ------------
// One warp per node. Rows padded to multiples of 4 -> every group full, no
// serial tail. Per group: ONE int4 row load + ONE float4 weight load
// (warp-uniform broadcasts), then 4 pipelined feature-row loads.
__global__ __launch_bounds__(256) void k_spmm(
    const float* __restrict__ feat, const int* __restrict__ rows,
    const float* __restrict__ bias, float* __restrict__ out)
{
    int node = (int)((blockIdx.x * blockDim.x + threadIdx.x) >> 5);
    if (node >= NN) return;
    int lane = threadIdx.x & 31;

    int start = g_rowptr[node];
    int end   = g_rowptr[node + 1];
    const float4* f4 = (const float4*)feat;

    float ax = 0.f, ay = 0.f, az = 0.f, aw = 0.f;
    for (int k = start; k < end; k += 4) {
        int4   r4 = *(const int4*)  &rows[k];
        float4 w4 = *(const float4*)&g_w [k];
        float4 v0 = f4[(size_t)r4.x * 32 + lane];
        float4 v1 = f4[(size_t)r4.y * 32 + lane];
        float4 v2 = f4[(size_t)r4.z * 32 + lane];
        float4 v3 = f4[(size_t)r4.w * 32 + lane];
        ax = fmaf(w4.x, v0.x, ax); ay = fmaf(w4.x, v0.y, ay);
        az = fmaf(w4.x, v0.z, az); aw = fmaf(w4.x, v0.w, aw);
        ax = fmaf(w4.y, v1.x, ax); ay = fmaf(w4.y, v1.y, ay);
        az = fmaf(w4.y, v1.z, az); aw = fmaf(w4.y, v1.w, aw);
        ax = fmaf(w4.z, v2.x, ax); ay = fmaf(w4.z, v2.y, ay);
        az = fmaf(w4.z, v2.z, az); aw = fmaf(w4.z, v2.w, aw);
        ax = fmaf(w4.w, v3.x, ax); ay = fmaf(w4.w, v3.y, ay);
        az = fmaf(w4.w, v3.z, az); aw = fmaf(w4.w, v3.w, aw);
    }

    float di = g_dinv[node];
    float4 b = __ldg((const float4*)bias + lane);
    float4 o;
    o.x = fmaxf(fmaf(di, ax, b.x), 0.f);
    o.y = fmaxf(fmaf(di, ay, b.y), 0.f);
    o.z = fmaxf(fmaf(di, az, b.z), 0.f);
    o.w = fmaxf(fmaf(di, aw, b.w), 0.f);
    __stcs((float4*)out + (size_t)node * 32 + lane, o);
}

// ---------------- launch ----------------------------------------------------
// R13 fork/join: CSR build (s2) overlapped with prep_wf + gemm1 (main).
extern "C" void kernel_launch(void* const* d_in, const int* in_sizes, int n_in,
                              void* d_out, int out_size) {
    const int*   x   = (const int*)d_in[0];
    const int*   src = (const int*)d_in[1];
    const int*   dst = src + NE;
    const float* emb = (const float*)d_in[2];
    const float* W1  = (const float*)d_in[3];
    const float* b1  = (const float*)d_in[4];
    const float* W2  = (const float*)d_in[5];
    const float* b2  = (const float*)d_in[6];
    float*       out = (float*)d_out;

    float *p_embW, *p_agg, *p_hw;
    uint4 *p_Wf;
    int   *p_deg, *p_r1, *p_r2;
    cudaGetSymbolAddress((void**)&p_embW, g_embW);
    cudaGetSymbolAddress((void**)&p_agg,  g_agg);
    cudaGetSymbolAddress((void**)&p_hw,   g_hw);
    cudaGetSymbolAddress((void**)&p_Wf,   g_Wf);
    cudaGetSymbolAddress((void**)&p_deg,  g_deg);
    cudaGetSymbolAddress((void**)&p_r1,   g_r1);
    cudaGetSymbolAddress((void**)&p_r2,   g_r2);

    cudaFuncSetAttribute(k_gemm_mma, cudaFuncAttributeMaxDynamicSharedMemorySize, SMEM_GEMM);

    cudaStream_t s2;
    cudaEvent_t ev_fork, ev_join;
    cudaStreamCreateWithFlags(&s2, cudaStreamNonBlocking);
    cudaEventCreateWithFlags(&ev_fork, cudaEventDisableTiming);
    cudaEventCreateWithFlags(&ev_join, cudaEventDisableTiming);

    cudaEventRecord(ev_fork, 0);
    cudaStreamWaitEvent(s2, ev_fork, 0);

    // Phase 1: CSR (s2)  ||  prep_wf + gemm1 (main)
    cudaMemsetAsync(p_deg, 0, NN * sizeof(int), s2);
    k_count_deg <<<(NE + 255) / 256, 256, 0, s2>>>(dst);               // #1
    k_prep_wf   <<<(2 * 16 * 8 * 32 + 255) / 256, 256>>>(W1, W2);      // #2
    k_scan_fused<<<1, 1024, 0, s2>>>();                                // #3
    k_gemm_mma  <<<TILES1, 256, SMEM_GEMM>>>(emb, p_Wf, p_embW, NV);   // #4 <- profiled
    k_fill_init <<<(NN + 255) / 256, 256, 0, s2>>>(x);                 // #5
    k_fill_edges<<<(NE + 255) / 256, 256, 0, s2>>>(src, dst, x);       // #6

    cudaEventRecord(ev_join, s2);
    cudaStreamWaitEvent(0, ev_join, 0);

    k_spmm      <<<(NN + 7) / 8, 256>>>(p_embW, p_r1, b1, p_agg);      // #7
    k_gemm_mma  <<<TILES2, 256, SMEM_GEMM>>>(p_agg, p_Wf + 16 * 8 * 32, p_hw, NN); // #8
    k_spmm      <<<(NN + 7) / 8, 256>>>(p_hw, p_r2, b2, out);          // #9
}

// round 16
// speedup vs baseline: 1.2748x; 1.1206x over previous
#include <cuda_runtime.h>
#include <cuda_bf16.h>
#include <cuda_fp16.h>
#include <cstdint>

#define NN 100000
#define NE 600000
#define NV 50000
#define DIM 128
#define NNZ (NE + NN)
#define CHUNK ((NN + 1023) / 1024)   // 98

#define TILES1 ((NV + 63) / 64)     // 782
#define TILES2 ((NN + 63) / 64)     // 1563

// ---------------- scratch (static device globals; no allocation) ----------
__device__ int    g_deg[NN];                 // EDGE degree only (self-loop folded)
__device__ int    g_rowptr[NN + 1];
__device__ int    g_cursor[NN];
__device__ int    g_col[NNZ];
__device__ float  g_dinv[NN];
__device__ uint4  g_Wf[2 * 16 * 8 * 32];     // W frags hi/lo packed
__device__ __half g_embW[(size_t)NV * DIM];  // emb @ W1  (fp16, 12.8 MB)
__device__ float  g_agg [(size_t)NN * DIM];  // layer-1 output h1 (fp32)
__device__ __half g_hw  [(size_t)NN * DIM];  // layer-2 pre-agg (fp16, 25.6 MB)

// ---------------- degree / CSR build ---------------------------------------
__global__ void k_count_deg(const int* __restrict__ dst) {
    int e = blockIdx.x * blockDim.x + threadIdx.x;
    if (e < NE) atomicAdd(&g_deg[dst[e]], 1);
}
__global__ __launch_bounds__(1024) void k_scan_fused() {
    __shared__ int s[1024];
    int tid = threadIdx.x;
    int lo = tid * CHUNK;
    int hi = lo + CHUNK; if (hi > NN) hi = NN;
    int sum = 0;
    #pragma unroll 4
    for (int i = lo; i < hi; i++) sum += g_deg[i] + 1;
    s[tid] = sum;
    __syncthreads();
    #pragma unroll
    for (int off = 1; off < 1024; off <<= 1) {
        int t = (tid >= off) ? s[tid - off] : 0;
        __syncthreads();
        s[tid] += t;
        __syncthreads();
    }
    int run = (tid == 0) ? 0 : s[tid - 1];
    #pragma unroll 4
    for (int i = lo; i < hi; i++) { g_rowptr[i] = run; run += g_deg[i] + 1; }
    if (tid == 1023) g_rowptr[NN] = run;
}
__global__ void k_fill_init() {
    int i = blockIdx.x * blockDim.x + threadIdx.x;
    if (i < NN) {
        int base = g_rowptr[i];
        g_col[base] = i;
        g_cursor[i] = base + 1;
        g_dinv[i] = rsqrtf((float)(g_deg[i] + 1));
    }
}
__global__ void k_fill_edges(const int* __restrict__ src, const int* __restrict__ dst) {
    int e = blockIdx.x * blockDim.x + threadIdx.x;
    if (e < NE) {
        int pos = atomicAdd(&g_cursor[dst[e]], 1);
        g_col[pos] = src[e];
    }
}

// ---------------- helpers ---------------------------------------------------
__device__ __forceinline__ uint32_t pack_bf16(float lo_val, float hi_val) {
    uint32_t d;
    asm("cvt.rn.bf16x2.f32 %0, %1, %2;" : "=r"(d) : "f"(hi_val), "f"(lo_val));
    return d;
}
__device__ __forceinline__ float bf16lo_to_f32(uint32_t p) { return __uint_as_float(p << 16); }
__device__ __forceinline__ float bf16hi_to_f32(uint32_t p) { return __uint_as_float(p & 0xFFFF0000u); }

__device__ __forceinline__ void mma_bf16(float* c, const uint32_t* a, uint32_t b0, uint32_t b1) {
    asm volatile(
        "mma.sync.aligned.m16n8k16.row.col.f32.bf16.bf16.f32 "
        "{%0,%1,%2,%3}, {%4,%5,%6,%7}, {%8,%9}, {%0,%1,%2,%3};"
        : "+f"(c[0]), "+f"(c[1]), "+f"(c[2]), "+f"(c[3])
        : "r"(a[0]), "r"(a[1]), "r"(a[2]), "r"(a[3]), "r"(b0), "r"(b1));
}

__global__ void k_prep_wf(const float* __restrict__ W1, const float* __restrict__ W2) {
    int gid = blockIdx.x * blockDim.x + threadIdx.x;   // 8192 total
    if (gid >= 2 * 16 * 8 * 32) return;
    int lane  = gid & 31;
    int kt    = (gid >> 5) & 7;
    int nt    = (gid >> 8) & 15;
    int layer = gid >> 12;
    const float* W = layer ? W2 : W1;
    int n  = nt * 8 + (lane >> 2);
    int k0 = kt * 16 + (lane & 3) * 2;

    float v[4];
    v[0] = W[(k0    ) * DIM + n];
    v[1] = W[(k0 + 1) * DIM + n];
    v[2] = W[(k0 + 8) * DIM + n];
    v[3] = W[(k0 + 9) * DIM + n];
    float h[4], l[4];
    #pragma unroll
    for (int j = 0; j < 4; j++) {
        __nv_bfloat16 hb = __float2bfloat16_rn(v[j]);
        h[j] = __bfloat162float(hb);
        l[j] = v[j] - h[j];
    }
    g_Wf[gid] = make_uint4(pack_bf16(h[0], h[1]), pack_bf16(h[2], h[3]),
                           pack_bf16(l[0], l[1]), pack_bf16(l[2], l[3]));
}

// ---------------- GEMM via mma.sync bf16 split (3-pass), fp16 output -------
#define SA_STRIDE 68
#define SMEM_GEMM (2 * 64 * SA_STRIDE * 4)    // 34816 B

__global__ __launch_bounds__(256, 3) void k_gemm_mma(
    const float* __restrict__ A, const uint4* __restrict__ Wf,
    __half* __restrict__ C, int M)
{
    extern __shared__ uint32_t sAu[];
    uint32_t* sAh = sAu;
    uint32_t* sAl = sAu + 64 * SA_STRIDE;
    int tid = threadIdx.x;
    int wid = tid >> 5;
    int lane = tid & 31;
    int row0 = blockIdx.x * 64;
    int rows_left = M - row0;

    {
        const float4* Av = (const float4*)(A + (size_t)row0 * DIM);
        #pragma unroll
        for (int i = 0; i < 8; i++) {
            int idx = tid + i * 256;
            int r = idx >> 5, c4 = idx & 31;
            float4 v = make_float4(0.f, 0.f, 0.f, 0.f);
            if (r < rows_left) v = __ldcs(Av + idx);
            uint32_t h0 = pack_bf16(v.x, v.y);
            uint32_t h1 = pack_bf16(v.z, v.w);
            uint32_t l0 = pack_bf16(v.x - bf16lo_to_f32(h0), v.y - bf16hi_to_f32(h0));
            uint32_t l1 = pack_bf16(v.z - bf16lo_to_f32(h1), v.w - bf16hi_to_f32(h1));
            *(uint2*)&sAh[r * SA_STRIDE + c4 * 2] = make_uint2(h0, h1);
            *(uint2*)&sAl[r * SA_STRIDE + c4 * 2] = make_uint2(l0, l1);
        }
    }
    __syncthreads();

    int wr = wid >> 2;
    int wc = wid & 3;
    int q  = lane >> 2;
    int w  = lane & 3;

    float acc[2][4][4];
    #pragma unroll
    for (int m = 0; m < 2; m++)
        #pragma unroll
        for (int j = 0; j < 4; j++)
            acc[m][j][0] = acc[m][j][1] = acc[m][j][2] = acc[m][j][3] = 0.f;

    int rA = (wr * 32 + q) * SA_STRIDE;
    const uint4* pb0 = Wf + wc * 1024 + lane;

    #pragma unroll
    for (int kt = 0; kt < 8; kt++) {
        int kp = kt * 8 + w;
        uint32_t ah0[4], al0[4], ah1[4], al1[4];
        ah0[0] = sAh[rA + kp];                    ah0[1] = sAh[rA + 8  * SA_STRIDE + kp];
        ah0[2] = sAh[rA + kp + 4];                ah0[3] = sAh[rA + 8  * SA_STRIDE + kp + 4];
        ah1[0] = sAh[rA + 16 * SA_STRIDE + kp];   ah1[1] = sAh[rA + 24 * SA_STRIDE + kp];
        ah1[2] = sAh[rA + 16 * SA_STRIDE + kp+4]; ah1[3] = sAh[rA + 24 * SA_STRIDE + kp + 4];
        al0[0] = sAl[rA + kp];                    al0[1] = sAl[rA + 8  * SA_STRIDE + kp];
        al0[2] = sAl[rA + kp + 4];                al0[3] = sAl[rA + 8  * SA_STRIDE + kp + 4];
        al1[0] = sAl[rA + 16 * SA_STRIDE + kp];   al1[1] = sAl[rA + 24 * SA_STRIDE + kp];
        al1[2] = sAl[rA + 16 * SA_STRIDE + kp+4]; al1[3] = sAl[rA + 24 * SA_STRIDE + kp + 4];

        const uint4* pb = pb0 + kt * 32;
        uint4 b[4];
        #pragma unroll
        for (int j = 0; j < 4; j++)
            b[j] = __ldg(pb + j * 256);

        #pragma unroll
        for (int j = 0; j < 4; j++) {
            mma_bf16(acc[0][j], ah0, b[j].x, b[j].y);
            mma_bf16(acc[1][j], ah1, b[j].x, b[j].y);
        }
        #pragma unroll
        for (int j = 0; j < 4; j++) {
            mma_bf16(acc[0][j], al0, b[j].x, b[j].y);
            mma_bf16(acc[1][j], al1, b[j].x, b[j].y);
        }
        #pragma unroll
        for (int j = 0; j < 4; j++) {
            mma_bf16(acc[0][j], ah0, b[j].z, b[j].w);
            mma_bf16(acc[1][j], ah1, b[j].z, b[j].w);
        }
    }

    __half2* Ch = (__half2*)C;
    #pragma unroll
    for (int m = 0; m < 2; m++) {
        int rr0 = row0 + wr * 32 + m * 16 + q;
        int rr1 = rr0 + 8;
        #pragma unroll
        for (int j = 0; j < 4; j++) {
            int col = (wc * 4 + j) * 8 + w * 2;
            if (rr0 < M)
                Ch[((size_t)rr0 * DIM + col) >> 1] = __floats2half2_rn(acc[m][j][0], acc[m][j][1]);
            if (rr1 < M)
                Ch[((size_t)rr1 * DIM + col) >> 1] = __floats2half2_rn(acc[m][j][2], acc[m][j][3]);
        }
    }
}

// ---------------- SpMM gather over fp16 features (R13 structure) ------------
// One warp per node; lane handles 4 cols = 2 half2 = one uint2 load (8B).
template<bool LAYER1, typename OUTSTORE>
__global__ __launch_bounds__(256) void k_spmm(
    const __half* __restrict__ feat, const int* __restrict__ x,
    const float* __restrict__ bias, OUTSTORE* __restrict__ out_)
{
    int node = (int)((blockIdx.x * blockDim.x + threadIdx.x) >> 5);
    if (node >= NN) return;
    int lane = threadIdx.x & 31;

    int start = g_rowptr[node];
    int end   = g_rowptr[node + 1];
    const uint2* f2 = (const uint2*)feat;     // row stride = 32 uint2

    float ax = 0.f, ay = 0.f, az = 0.f, aw = 0.f;
    int k = start;
    for (; k + 3 < end; k += 4) {
        int c0 = g_col[k],     c1 = g_col[k + 1];
        int c2 = g_col[k + 2], c3 = g_col[k + 3];
        float w0 = g_dinv[c0], w1 = g_dinv[c1];
        float w2 = g_dinv[c2], w3 = g_dinv[c3];
        int r0 = LAYER1 ? x[c0] : c0;
        int r1 = LAYER1 ? x[c1] : c1;
        int r2 = LAYER1 ? x[c2] : c2;
        int r3 = LAYER1 ? x[c3] : c3;
        uint2 u0 = f2[(size_t)r0 * 32 + lane];
        uint2 u1 = f2[(size_t)r1 * 32 + lane];
        uint2 u2 = f2[(size_t)r2 * 32 + lane];
        uint2 u3 = f2[(size_t)r3 * 32 + lane];
        float2 a0 = __half22float2(*(__half2*)&u0.x), b0 = __half22float2(*(__half2*)&u0.y);
        float2 a1 = __half22float2(*(__half2*)&u1.x), b1 = __half22float2(*(__half2*)&u1.y);
        float2 a2 = __half22float2(*(__half2*)&u2.x), b2 = __half22float2(*(__half2*)&u2.y);
        float2 a3 = __half22float2(*(__half2*)&u3.x), b3 = __half22float2(*(__half2*)&u3.y);
        ax = fmaf(w0, a0.x, ax); ay = fmaf(w0, a0.y, ay);
        az = fmaf(w0, b0.x, az); aw = fmaf(w0, b0.y, aw);
        ax = fmaf(w1, a1.x, ax); ay = fmaf(w1, a1.y, ay);
        az = fmaf(w1, b1.x, az); aw = fmaf(w1, b1.y, aw);
        ax = fmaf(w2, a2.x, ax); ay = fmaf(w2, a2.y, ay);
        az = fmaf(w2, b2.x, az); aw = fmaf(w2, b2.y, aw);
        ax = fmaf(w3, a3.x, ax); ay = fmaf(w3, a3.y, ay);
        az = fmaf(w3, b3.x, az); aw = fmaf(w3, b3.y, aw);
    }
    for (; k < end; k++) {
        int c = g_col[k];
        float w = g_dinv[c];
        int r = LAYER1 ? x[c] : c;
        uint2 u = f2[(size_t)r * 32 + lane];
        float2 a = __half22float2(*(__half2*)&u.x), b = __half22float2(*(__half2*)&u.y);
        ax = fmaf(w, a.x, ax); ay = fmaf(w, a.y, ay);
        az = fmaf(w, b.x, az); aw = fmaf(w, b.y, aw);
    }

    float di = g_dinv[node];
    float4 b = __ldg((const float4*)bias + lane);
    float4 o;
    o.x = fmaxf(fmaf(di, ax, b.x), 0.f);
    o.y = fmaxf(fmaf(di, ay, b.y), 0.f);
    o.z = fmaxf(fmaf(di, az, b.z), 0.f);
    o.w = fmaxf(fmaf(di, aw, b.w), 0.f);
    __stcs((float4*)out_ + (size_t)node * 32 + lane, o);   // fp32 streaming store
}

// ---------------- launch ----------------------------------------------------
// R13 fork/join: CSR build (s2) overlapped with prep_wf + gemm1 (main).
extern "C" void kernel_launch(void* const* d_in, const int* in_sizes, int n_in,
                              void* d_out, int out_size) {
    const int*   x   = (const int*)d_in[0];
    const int*   src = (const int*)d_in[1];
    const int*   dst = src + NE;
    const float* emb = (const float*)d_in[2];
    const float* W1  = (const float*)d_in[3];
    const float* b1  = (const float*)d_in[4];
    const float* W2  = (const float*)d_in[5];
    const float* b2  = (const float*)d_in[6];
    float*       out = (float*)d_out;

    float *p_agg;
    __half *p_embW, *p_hw;
    uint4 *p_Wf;
    int   *p_deg;
    cudaGetSymbolAddress((void**)&p_embW, g_embW);
    cudaGetSymbolAddress((void**)&p_agg,  g_agg);
    cudaGetSymbolAddress((void**)&p_hw,   g_hw);
    cudaGetSymbolAddress((void**)&p_Wf,   g_Wf);
    cudaGetSymbolAddress((void**)&p_deg,  g_deg);

    cudaFuncSetAttribute(k_gemm_mma, cudaFuncAttributeMaxDynamicSharedMemorySize, SMEM_GEMM);

    cudaStream_t s2;
    cudaEvent_t ev_fork, ev_join;
    cudaStreamCreateWithFlags(&s2, cudaStreamNonBlocking);
    cudaEventCreateWithFlags(&ev_fork, cudaEventDisableTiming);
    cudaEventCreateWithFlags(&ev_join, cudaEventDisableTiming);

    cudaEventRecord(ev_fork, 0);
    cudaStreamWaitEvent(s2, ev_fork, 0);

    // Phase 1: CSR (s2)  ||  prep_wf + gemm1 (main)
    cudaMemsetAsync(p_deg, 0, NN * sizeof(int), s2);
    k_count_deg <<<(NE + 255) / 256, 256, 0, s2>>>(dst);                // #1
    k_prep_wf   <<<(2 * 16 * 8 * 32 + 255) / 256, 256>>>(W1, W2);       // #2
    k_scan_fused<<<1, 1024, 0, s2>>>();                                 // #3
    k_gemm_mma  <<<TILES1, 256, SMEM_GEMM>>>(emb, p_Wf, p_embW, NV);    // #4 <- profiled
    k_fill_init <<<(NN + 255) / 256, 256, 0, s2>>>();                   // #5
    k_fill_edges<<<(NE + 255) / 256, 256, 0, s2>>>(src, dst);           // #6

    cudaEventRecord(ev_join, s2);
    cudaStreamWaitEvent(0, ev_join, 0);

    k_spmm<true><<<(NN + 7) / 8, 256>>>(p_embW, x, b1, p_agg);          // #7
    k_gemm_mma  <<<TILES2, 256, SMEM_GEMM>>>(p_agg, p_Wf + 16 * 8 * 32, p_hw, NN); // #8
    k_spmm<false><<<(NN + 7) / 8, 256>>>(p_hw, x, b2, out);             // #9
}

// round 17
// speedup vs baseline: 1.2831x; 1.0065x over previous
#include <cuda_runtime.h>
#include <cuda_bf16.h>
#include <cuda_fp16.h>
#include <cstdint>

#define NN 100000
#define NE 600000
#define NV 50000
#define DIM 128
#define NNZ (NE + NN)
#define CHUNK ((NN + 1023) / 1024)   // 98

#define TILES1 ((NV + 63) / 64)     // 782
#define TILES2 ((NN + 63) / 64)     // 1563

// ---------------- scratch (static device globals; no allocation) ----------
__device__ int    g_deg[NN];                 // EDGE degree only (self-loop folded)
__device__ int    g_rowptr[NN + 1];
__device__ int    g_cursor[NN];
__device__ int    g_col[NNZ];
__device__ float  g_dinv[NN];
__device__ uint4  g_Wf[2 * 16 * 8 * 32];     // W frags hi/lo packed
__device__ __half g_embW[(size_t)NV * DIM];  // emb @ W1  (fp16, 12.8 MB)
__device__ __half g_agg [(size_t)NN * DIM];  // layer-1 output h1 (fp16, 25.6 MB)
__device__ __half g_hw  [(size_t)NN * DIM];  // layer-2 pre-agg (fp16, 25.6 MB)

// ---------------- degree / CSR build ---------------------------------------
__global__ void k_count_deg(const int* __restrict__ dst) {
    int e = blockIdx.x * blockDim.x + threadIdx.x;
    if (e < NE) atomicAdd(&g_deg[dst[e]], 1);
}
__global__ __launch_bounds__(1024) void k_scan_fused() {
    __shared__ int s[1024];
    int tid = threadIdx.x;
    int lo = tid * CHUNK;
    int hi = lo + CHUNK; if (hi > NN) hi = NN;
    int sum = 0;
    #pragma unroll 4
    for (int i = lo; i < hi; i++) sum += g_deg[i] + 1;
    s[tid] = sum;
    __syncthreads();
    #pragma unroll
    for (int off = 1; off < 1024; off <<= 1) {
        int t = (tid >= off) ? s[tid - off] : 0;
        __syncthreads();
        s[tid] += t;
        __syncthreads();
    }
    int run = (tid == 0) ? 0 : s[tid - 1];
    #pragma unroll 4
    for (int i = lo; i < hi; i++) { g_rowptr[i] = run; run += g_deg[i] + 1; }
    if (tid == 1023) g_rowptr[NN] = run;
}
__global__ void k_fill_init() {
    int i = blockIdx.x * blockDim.x + threadIdx.x;
    if (i < NN) {
        int base = g_rowptr[i];
        g_col[base] = i;
        g_cursor[i] = base + 1;
        g_dinv[i] = rsqrtf((float)(g_deg[i] + 1));
    }
}
__global__ void k_fill_edges(const int* __restrict__ src, const int* __restrict__ dst) {
    int e = blockIdx.x * blockDim.x + threadIdx.x;
    if (e < NE) {
        int pos = atomicAdd(&g_cursor[dst[e]], 1);
        g_col[pos] = src[e];
    }
}

// ---------------- helpers ---------------------------------------------------
__device__ __forceinline__ uint32_t pack_bf16(float lo_val, float hi_val) {
    uint32_t d;
    asm("cvt.rn.bf16x2.f32 %0, %1, %2;" : "=r"(d) : "f"(hi_val), "f"(lo_val));
    return d;
}
__device__ __forceinline__ float bf16lo_to_f32(uint32_t p) { return __uint_as_float(p << 16); }
__device__ __forceinline__ float bf16hi_to_f32(uint32_t p) { return __uint_as_float(p & 0xFFFF0000u); }

__device__ __forceinline__ void mma_bf16(float* c, const uint32_t* a, uint32_t b0, uint32_t b1) {
    asm volatile(
        "mma.sync.aligned.m16n8k16.row.col.f32.bf16.bf16.f32 "
        "{%0,%1,%2,%3}, {%4,%5,%6,%7}, {%8,%9}, {%0,%1,%2,%3};"
        : "+f"(c[0]), "+f"(c[1]), "+f"(c[2]), "+f"(c[3])
        : "r"(a[0]), "r"(a[1]), "r"(a[2]), "r"(a[3]), "r"(b0), "r"(b1));
}
// split one fp32 pair into bf16 hi/lo packed words
__device__ __forceinline__ void split2(float fx, float fy, uint32_t& h, uint32_t& l) {
    h = pack_bf16(fx, fy);
    l = pack_bf16(fx - bf16lo_to_f32(h), fy - bf16hi_to_f32(h));
}

__global__ void k_prep_wf(const float* __restrict__ W1, const float* __restrict__ W2) {
    int gid = blockIdx.x * blockDim.x + threadIdx.x;   // 8192 total
    if (gid >= 2 * 16 * 8 * 32) return;
    int lane  = gid & 31;
    int kt    = (gid >> 5) & 7;
    int nt    = (gid >> 8) & 15;
    int layer = gid >> 12;
    const float* W = layer ? W2 : W1;
    int n  = nt * 8 + (lane >> 2);
    int k0 = kt * 16 + (lane & 3) * 2;

    float v[4];
    v[0] = W[(k0    ) * DIM + n];
    v[1] = W[(k0 + 1) * DIM + n];
    v[2] = W[(k0 + 8) * DIM + n];
    v[3] = W[(k0 + 9) * DIM + n];
    float h[4], l[4];
    #pragma unroll
    for (int j = 0; j < 4; j++) {
        __nv_bfloat16 hb = __float2bfloat16_rn(v[j]);
        h[j] = __bfloat162float(hb);
        l[j] = v[j] - h[j];
    }
    g_Wf[gid] = make_uint4(pack_bf16(h[0], h[1]), pack_bf16(h[2], h[3]),
                           pack_bf16(l[0], l[1]), pack_bf16(l[2], l[3]));
}

// ---------------- GEMM via mma.sync bf16 split (3-pass), fp16 output -------
// AHALF: A matrix stored fp16 (gemm2); else fp32 (gemm1).
#define SA_STRIDE 68
#define SMEM_GEMM (2 * 64 * SA_STRIDE * 4)    // 34816 B

template<bool AHALF>
__global__ __launch_bounds__(256, 3) void k_gemm_mma(
    const void* __restrict__ A_, const uint4* __restrict__ Wf,
    __half* __restrict__ C, int M)
{
    extern __shared__ uint32_t sAu[];
    uint32_t* sAh = sAu;
    uint32_t* sAl = sAu + 64 * SA_STRIDE;
    int tid = threadIdx.x;
    int wid = tid >> 5;
    int lane = tid & 31;
    int row0 = blockIdx.x * 64;
    int rows_left = M - row0;

    if (AHALF) {
        // fp16 A: row = 128 halves = 16 uint4; thread loads 8 halves (uint4)
        const uint4* Av = (const uint4*)((const __half*)A_ + (size_t)row0 * DIM);
        #pragma unroll
        for (int i = 0; i < 4; i++) {
            int idx = tid + i * 256;           // 1024 uint4 total
            int r = idx >> 4, c8 = idx & 15;   // 16 uint4 per row
            uint4 u = make_uint4(0u, 0u, 0u, 0u);
            if (r < rows_left) u = __ldcs(Av + idx);
            uint32_t hw_[4], lw_[4];
            const uint32_t* up = &u.x;
            #pragma unroll
            for (int j = 0; j < 4; j++) {
                float2 f = __half22float2(*(__half2*)&up[j]);
                split2(f.x, f.y, hw_[j], lw_[j]);
            }
            *(uint4*)&sAh[r * SA_STRIDE + c8 * 4] = make_uint4(hw_[0], hw_[1], hw_[2], hw_[3]);
            *(uint4*)&sAl[r * SA_STRIDE + c8 * 4] = make_uint4(lw_[0], lw_[1], lw_[2], lw_[3]);
        }
    } else {
        const float4* Av = (const float4*)((const float*)A_ + (size_t)row0 * DIM);
        #pragma unroll
        for (int i = 0; i < 8; i++) {
            int idx = tid + i * 256;
            int r = idx >> 5, c4 = idx & 31;
            float4 v = make_float4(0.f, 0.f, 0.f, 0.f);
            if (r < rows_left) v = __ldcs(Av + idx);
            uint32_t h0, h1, l0, l1;
            split2(v.x, v.y, h0, l0);
            split2(v.z, v.w, h1, l1);
            *(uint2*)&sAh[r * SA_STRIDE + c4 * 2] = make_uint2(h0, h1);
            *(uint2*)&sAl[r * SA_STRIDE + c4 * 2] = make_uint2(l0, l1);
        }
    }
    __syncthreads();

    int wr = wid >> 2;
    int wc = wid & 3;
    int q  = lane >> 2;
    int w  = lane & 3;

    float acc[2][4][4];
    #pragma unroll
    for (int m = 0; m < 2; m++)
        #pragma unroll
        for (int j = 0; j < 4; j++)
            acc[m][j][0] = acc[m][j][1] = acc[m][j][2] = acc[m][j][3] = 0.f;

    int rA = (wr * 32 + q) * SA_STRIDE;
    const uint4* pb0 = Wf + wc * 1024 + lane;

    #pragma unroll
    for (int kt = 0; kt < 8; kt++) {
        int kp = kt * 8 + w;
        uint32_t ah0[4], al0[4], ah1[4], al1[4];
        ah0[0] = sAh[rA + kp];                    ah0[1] = sAh[rA + 8  * SA_STRIDE + kp];
        ah0[2] = sAh[rA + kp + 4];                ah0[3] = sAh[rA + 8  * SA_STRIDE + kp + 4];
        ah1[0] = sAh[rA + 16 * SA_STRIDE + kp];   ah1[1] = sAh[rA + 24 * SA_STRIDE + kp];
        ah1[2] = sAh[rA + 16 * SA_STRIDE + kp+4]; ah1[3] = sAh[rA + 24 * SA_STRIDE + kp + 4];
        al0[0] = sAl[rA + kp];                    al0[1] = sAl[rA + 8  * SA_STRIDE + kp];
        al0[2] = sAl[rA + kp + 4];                al0[3] = sAl[rA + 8  * SA_STRIDE + kp + 4];
        al1[0] = sAl[rA + 16 * SA_STRIDE + kp];   al1[1] = sAl[rA + 24 * SA_STRIDE + kp];
        al1[2] = sAl[rA + 16 * SA_STRIDE + kp+4]; al1[3] = sAl[rA + 24 * SA_STRIDE + kp + 4];

        const uint4* pb = pb0 + kt * 32;
        uint4 b[4];
        #pragma unroll
        for (int j = 0; j < 4; j++)
            b[j] = __ldg(pb + j * 256);

        #pragma unroll
        for (int j = 0; j < 4; j++) {
            mma_bf16(acc[0][j], ah0, b[j].x, b[j].y);
            mma_bf16(acc[1][j], ah1, b[j].x, b[j].y);
        }
        #pragma unroll
        for (int j = 0; j < 4; j++) {
            mma_bf16(acc[0][j], al0, b[j].x, b[j].y);
            mma_bf16(acc[1][j], al1, b[j].x, b[j].y);
        }
        #pragma unroll
        for (int j = 0; j < 4; j++) {
            mma_bf16(acc[0][j], ah0, b[j].z, b[j].w);
            mma_bf16(acc[1][j], ah1, b[j].z, b[j].w);
        }
    }

    __half2* Ch = (__half2*)C;
    #pragma unroll
    for (int m = 0; m < 2; m++) {
        int rr0 = row0 + wr * 32 + m * 16 + q;
        int rr1 = rr0 + 8;
        #pragma unroll
        for (int j = 0; j < 4; j++) {
            int col = (wc * 4 + j) * 8 + w * 2;
            if (rr0 < M)
                Ch[((size_t)rr0 * DIM + col) >> 1] = __floats2half2_rn(acc[m][j][0], acc[m][j][1]);
            if (rr1 < M)
                Ch[((size_t)rr1 * DIM + col) >> 1] = __floats2half2_rn(acc[m][j][2], acc[m][j][3]);
        }
    }
}

// ---------------- SpMM gather over fp16 features ----------------------------
// OUTHALF: write fp16 (spmm1 -> agg); else fp32 (spmm2 -> d_out).
template<bool LAYER1, bool OUTHALF>
__global__ __launch_bounds__(256) void k_spmm(
    const __half* __restrict__ feat, const int* __restrict__ x,
    const float* __restrict__ bias, void* __restrict__ out_)
{
    int node = (int)((blockIdx.x * blockDim.x + threadIdx.x) >> 5);
    if (node >= NN) return;
    int lane = threadIdx.x & 31;

    int start = g_rowptr[node];
    int end   = g_rowptr[node + 1];
    const uint2* f2 = (const uint2*)feat;     // row stride = 32 uint2

    float ax = 0.f, ay = 0.f, az = 0.f, aw = 0.f;
    int k = start;
    for (; k + 3 < end; k += 4) {
        int c0 = g_col[k],     c1 = g_col[k + 1];
        int c2 = g_col[k + 2], c3 = g_col[k + 3];
        float w0 = g_dinv[c0], w1 = g_dinv[c1];
        float w2 = g_dinv[c2], w3 = g_dinv[c3];
        int r0 = LAYER1 ? x[c0] : c0;
        int r1 = LAYER1 ? x[c1] : c1;
        int r2 = LAYER1 ? x[c2] : c2;
        int r3 = LAYER1 ? x[c3] : c3;
        uint2 u0 = f2[(size_t)r0 * 32 + lane];
        uint2 u1 = f2[(size_t)r1 * 32 + lane];
        uint2 u2 = f2[(size_t)r2 * 32 + lane];
        uint2 u3 = f2[(size_t)r3 * 32 + lane];
        float2 a0 = __half22float2(*(__half2*)&u0.x), b0 = __half22float2(*(__half2*)&u0.y);
        float2 a1 = __half22float2(*(__half2*)&u1.x), b1 = __half22float2(*(__half2*)&u1.y);
        float2 a2 = __half22float2(*(__half2*)&u2.x), b2 = __half22float2(*(__half2*)&u2.y);
        float2 a3 = __half22float2(*(__half2*)&u3.x), b3 = __half22float2(*(__half2*)&u3.y);
        ax = fmaf(w0, a0.x, ax); ay = fmaf(w0, a0.y, ay);
        az = fmaf(w0, b0.x, az); aw = fmaf(w0, b0.y, aw);
        ax = fmaf(w1, a1.x, ax); ay = fmaf(w1, a1.y, ay);
        az = fmaf(w1, b1.x, az); aw = fmaf(w1, b1.y, aw);
        ax = fmaf(w2, a2.x, ax); ay = fmaf(w2, a2.y, ay);
        az = fmaf(w2, b2.x, az); aw = fmaf(w2, b2.y, aw);
        ax = fmaf(w3, a3.x, ax); ay = fmaf(w3, a3.y, ay);
        az = fmaf(w3, b3.x, az); aw = fmaf(w3, b3.y, aw);
    }
    for (; k < end; k++) {
        int c = g_col[k];
        float w = g_dinv[c];
        int r = LAYER1 ? x[c] : c;
        uint2 u = f2[(size_t)r * 32 + lane];
        float2 a = __half22float2(*(__half2*)&u.x), b = __half22float2(*(__half2*)&u.y);
        ax = fmaf(w, a.x, ax); ay = fmaf(w, a.y, ay);
        az = fmaf(w, b.x, az); aw = fmaf(w, b.y, aw);
    }

    float di = g_dinv[node];
    float4 b = __ldg((const float4*)bias + lane);
    float ox = fmaxf(fmaf(di, ax, b.x), 0.f);
    float oy = fmaxf(fmaf(di, ay, b.y), 0.f);
    float oz = fmaxf(fmaf(di, az, b.z), 0.f);
    float ow = fmaxf(fmaf(di, aw, b.w), 0.f);

    if (OUTHALF) {
        __half2 p0 = __floats2half2_rn(ox, oy);
        __half2 p1 = __floats2half2_rn(oz, ow);
        uint2 u = make_uint2(*(uint32_t*)&p0, *(uint32_t*)&p1);
        __stcs((uint2*)out_ + (size_t)node * 32 + lane, u);
    } else {
        __stcs((float4*)out_ + (size_t)node * 32 + lane, make_float4(ox, oy, oz, ow));
    }
}

// ---------------- launch ----------------------------------------------------
// R13 fork/join: CSR build (s2) overlapped with prep_wf + gemm1 (main).
extern "C" void kernel_launch(void* const* d_in, const int* in_sizes, int n_in,
                              void* d_out, int out_size) {
    const int*   x   = (const int*)d_in[0];
    const int*   src = (const int*)d_in[1];
    const int*   dst = src + NE;
    const float* emb = (const float*)d_in[2];
    const float* W1  = (const float*)d_in[3];
    const float* b1  = (const float*)d_in[4];
    const float* W2  = (const float*)d_in[5];
    const float* b2  = (const float*)d_in[6];
    float*       out = (float*)d_out;

    __half *p_embW, *p_agg, *p_hw;
    uint4 *p_Wf;
    int   *p_deg;
    cudaGetSymbolAddress((void**)&p_embW, g_embW);
    cudaGetSymbolAddress((void**)&p_agg,  g_agg);
    cudaGetSymbolAddress((void**)&p_hw,   g_hw);
    cudaGetSymbolAddress((void**)&p_Wf,   g_Wf);
    cudaGetSymbolAddress((void**)&p_deg,  g_deg);

    cudaFuncSetAttribute(k_gemm_mma<false>, cudaFuncAttributeMaxDynamicSharedMemorySize, SMEM_GEMM);
    cudaFuncSetAttribute(k_gemm_mma<true>,  cudaFuncAttributeMaxDynamicSharedMemorySize, SMEM_GEMM);

    cudaStream_t s2;
    cudaEvent_t ev_fork, ev_join;
    cudaStreamCreateWithFlags(&s2, cudaStreamNonBlocking);
    cudaEventCreateWithFlags(&ev_fork, cudaEventDisableTiming);
    cudaEventCreateWithFlags(&ev_join, cudaEventDisableTiming);

    cudaEventRecord(ev_fork, 0);
    cudaStreamWaitEvent(s2, ev_fork, 0);

    // Phase 1: CSR (s2)  ||  prep_wf + gemm1 (main)
    cudaMemsetAsync(p_deg, 0, NN * sizeof(int), s2);
    k_count_deg <<<(NE + 255) / 256, 256, 0, s2>>>(dst);                    // #1
    k_prep_wf   <<<(2 * 16 * 8 * 32 + 255) / 256, 256>>>(W1, W2);           // #2
    k_scan_fused<<<1, 1024, 0, s2>>>();                                     // #3
    k_gemm_mma<false><<<TILES1, 256, SMEM_GEMM>>>(emb, p_Wf, p_embW, NV);   // #4 <- profiled
    k_fill_init <<<(NN + 255) / 256, 256, 0, s2>>>();                       // #5
    k_fill_edges<<<(NE + 255) / 256, 256, 0, s2>>>(src, dst);               // #6

    cudaEventRecord(ev_join, s2);
    cudaStreamWaitEvent(0, ev_join, 0);

    k_spmm<true, true><<<(NN + 7) / 8, 256>>>(p_embW, x, b1, p_agg);        // #7
    k_gemm_mma<true><<<TILES2, 256, SMEM_GEMM>>>(p_agg, p_Wf + 16 * 8 * 32, p_hw, NN); // #8
    k_spmm<false, false><<<(NN + 7) / 8, 256>>>(p_hw, x, b2, out);          // #9
}